// round 15
// baseline (speedup 1.0000x reference)
#include <cuda_runtime.h>
#include <stdint.h>
#include <math.h>

#define SQ    2048
#define SKV   2048
#define DM    512
#define NH    8
#define DHEAD 64

// ---------------------------------------------------------------------------
// Scratch (device globals: allocation-guard safe)
// ---------------------------------------------------------------------------
__device__ float g_q[NH * SQ * DHEAD];          // [h][s][d] fp32
__device__ float g_k[NH * SKV * DHEAD];         // [h][t][d] fp32
__device__ float g_v[NH * SKV * DHEAD];         // [h][t][d] fp32
__device__ float g_concat[SQ * DM];             // [s][h*64 + c]
// bf16 split planes (hi + residual lo)
__device__ unsigned short g_qhi[NH * SQ * DHEAD],  g_qlo[NH * SQ * DHEAD];
__device__ unsigned short g_khi[NH * SKV * DHEAD], g_klo[NH * SKV * DHEAD];
__device__ unsigned short g_vthi[NH * DHEAD * SKV], g_vtlo[NH * DHEAD * SKV]; // [h][d][t]

// ---------------------------------------------------------------------------
// bf16 split helpers (verified in R12)
// ---------------------------------------------------------------------------
static __device__ __forceinline__ uint32_t bf2pack(float up, float dn) {
    uint32_t r;
    asm("cvt.rn.bf16x2.f32 %0, %1, %2;" : "=r"(r) : "f"(up), "f"(dn));
    return r;
}
static __device__ __forceinline__ float bf_up(uint32_t p) { return __uint_as_float(p & 0xffff0000u); }
static __device__ __forceinline__ float bf_dn(uint32_t p) { return __uint_as_float(p << 16); }
static __device__ __forceinline__ void split2(float x0, float x1, uint32_t& h, uint32_t& l) {
    h = bf2pack(x1, x0);
    l = bf2pack(x1 - bf_up(h), x0 - bf_dn(h));
}
static __device__ __forceinline__ void mma16816(float* d, const uint32_t* a,
                                                uint32_t b0, uint32_t b1) {
    asm("mma.sync.aligned.m16n8k16.row.col.f32.bf16.bf16.f32 "
        "{%0,%1,%2,%3}, {%4,%5,%6,%7}, {%8,%9}, {%0,%1,%2,%3};"
        : "+f"(d[0]), "+f"(d[1]), "+f"(d[2]), "+f"(d[3])
        : "r"(a[0]), "r"(a[1]), "r"(a[2]), "r"(a[3]), "r"(b0), "r"(b1));
}
static __device__ __forceinline__ void ldsm4(uint32_t addr, uint32_t* r) {
    asm volatile("ldmatrix.sync.aligned.m8n8.x4.shared.b16 {%0,%1,%2,%3}, [%4];"
                 : "=r"(r[0]), "=r"(r[1]), "=r"(r[2]), "=r"(r[3]) : "r"(addr));
}
static __device__ __forceinline__ uint32_t smem_u32(const void* p) {
    uint32_t r;
    asm("{ .reg .u64 t; cvta.to.shared.u64 t, %1; cvt.u32.u64 %0, t; }" : "=r"(r) : "l"(p));
    return r;
}

// ---------------------------------------------------------------------------
// Q/K/V projection GEMMs (unchanged; passing).
// ---------------------------------------------------------------------------
__global__ __launch_bounds__(128, 4) void proj_qkv_kernel(
    const float* __restrict__ X0, const float* __restrict__ W0, const float* __restrict__ b0,
    const float* __restrict__ X1, const float* __restrict__ W1, const float* __restrict__ b1,
    const float* __restrict__ X2, const float* __restrict__ W2, const float* __restrict__ b2)
{
    __shared__ float As[32][128];
    __shared__ float Bs[32][64];

    const float* X; const float* W; const float* b; float* out;
    if (blockIdx.z == 0)      { X = X0; W = W0; b = b0; out = g_q; }
    else if (blockIdx.z == 1) { X = X1; W = W1; b = b1; out = g_k; }
    else                      { X = X2; W = W2; b = b2; out = g_v; }

    const int h  = blockIdx.y;
    const int s0 = blockIdx.x * 128;
    const float* Wh = W + (size_t)h * DM * DHEAD;

    const int tid = threadIdx.x;
    const int ty8 = (tid >> 3) << 3;
    const int tx8 = (tid & 7) << 3;

    float acc[8][8];
    #pragma unroll
    for (int i = 0; i < 8; i++)
        #pragma unroll
        for (int j = 0; j < 8; j++) acc[i][j] = 0.f;

    const float* Xrow = X + (size_t)(s0 + tid) * DM;

    for (int kb = 0; kb < DM; kb += 32) {
        #pragma unroll
        for (int i = 0; i < 8; i++) {
            float4 v = *(const float4*)(Xrow + kb + i * 4);
            As[i * 4 + 0][tid] = v.x; As[i * 4 + 1][tid] = v.y;
            As[i * 4 + 2][tid] = v.z; As[i * 4 + 3][tid] = v.w;
        }
        #pragma unroll
        for (int i = 0; i < 4; i++) {
            int t  = tid + i * 128;
            int kk = t >> 4;
            int c4 = (t & 15) << 2;
            *(float4*)&Bs[kk][c4] = *(const float4*)(Wh + (size_t)(kb + kk) * DHEAD + c4);
        }
        __syncthreads();

        #pragma unroll 8
        for (int kk = 0; kk < 32; kk++) {
            float4 a0 = *(const float4*)&As[kk][ty8];
            float4 a1 = *(const float4*)&As[kk][ty8 + 4];
            float4 c0 = *(const float4*)&Bs[kk][tx8];
            float4 c1 = *(const float4*)&Bs[kk][tx8 + 4];
            float av[8] = {a0.x, a0.y, a0.z, a0.w, a1.x, a1.y, a1.z, a1.w};
            float bv[8] = {c0.x, c0.y, c0.z, c0.w, c1.x, c1.y, c1.z, c1.w};
            #pragma unroll
            for (int i = 0; i < 8; i++)
                #pragma unroll
                for (int j = 0; j < 8; j++)
                    acc[i][j] += av[i] * bv[j];
        }
        __syncthreads();
    }

    float4 bi0 = *(const float4*)(b + h * DHEAD + tx8);
    float4 bi1 = *(const float4*)(b + h * DHEAD + tx8 + 4);
    float bias[8] = {bi0.x, bi0.y, bi0.z, bi0.w, bi1.x, bi1.y, bi1.z, bi1.w};
    #pragma unroll
    for (int i = 0; i < 8; i++) {
        float* orow = out + ((size_t)h * SQ + s0 + ty8 + i) * DHEAD + tx8;
        *(float4*)orow = make_float4(acc[i][0] + bias[0], acc[i][1] + bias[1],
                                     acc[i][2] + bias[2], acc[i][3] + bias[3]);
        *(float4*)(orow + 4) = make_float4(acc[i][4] + bias[4], acc[i][5] + bias[5],
                                           acc[i][6] + bias[6], acc[i][7] + bias[7]);
    }
}

// ---------------------------------------------------------------------------
// Convert fp32 q/k -> hi/lo bf16 planes (unchanged; passing).
// ---------------------------------------------------------------------------
__global__ __launch_bounds__(256) void convert_qk_kernel(int which)
{
    const float* src   = which ? g_k : g_q;
    unsigned short* hi = which ? g_khi : g_qhi;
    unsigned short* lo = which ? g_klo : g_qlo;
    int i = blockIdx.x * 256 + threadIdx.x;
    float2 x = ((const float2*)src)[i];
    uint32_t hh, ll;
    split2(x.x, x.y, hh, ll);
    ((uint32_t*)hi)[i] = hh;
    ((uint32_t*)lo)[i] = ll;
}

// ---------------------------------------------------------------------------
// Convert + transpose V (unchanged; passing).
// ---------------------------------------------------------------------------
__global__ __launch_bounds__(256) void convert_vt_kernel()
{
    __shared__ float sm[64][65];
    const int h = blockIdx.y, t0 = blockIdx.x * 64;
    const int tid = threadIdx.x;
    const float* Vh = g_v + ((size_t)h * SKV + t0) * DHEAD;

    #pragma unroll
    for (int i = 0; i < 4; i++) {
        int fi = tid + i * 256;
        int t = fi >> 4, d4 = (fi & 15) << 2;
        float4 v = *(const float4*)(Vh + t * DHEAD + d4);
        sm[t][d4 + 0] = v.x; sm[t][d4 + 1] = v.y;
        sm[t][d4 + 2] = v.z; sm[t][d4 + 3] = v.w;
    }
    __syncthreads();

    uint32_t* oh = (uint32_t*)g_vthi;
    uint32_t* ol = (uint32_t*)g_vtlo;
    #pragma unroll
    for (int i = 0; i < 8; i++) {
        int oi = tid + i * 256;
        int d = oi >> 5, tp = oi & 31;
        float x0 = sm[2 * tp][d], x1 = sm[2 * tp + 1][d];
        uint32_t hh, ll;
        split2(x0, x1, hh, ll);
        size_t idx = ((size_t)h * 64 + d) * (SKV / 2) + (t0 >> 1) + tp;
        oh[idx] = hh;
        ol[idx] = ll;
    }
}

// ---------------------------------------------------------------------------
// bf16x3 tensor-core flash attention, smem-staged K/V + ldmatrix fragments.
// grid = (SQ/64, NH); block = 128 (4 warps x 16 q-rows); kv tile = 64.
// Swizzle: u32 offset = row*32 + ((f4*4) ^ ((row&7)<<2))  [16B-granular XOR]
// ---------------------------------------------------------------------------
__global__ __launch_bounds__(128) void attn_mma_kernel()
{
    __shared__ uint32_t sKh[64 * 32], sKl[64 * 32], sVh[64 * 32], sVl[64 * 32]; // 32 KB

    const int h    = blockIdx.y;
    const int tid  = threadIdx.x;
    const int wid  = tid >> 5, lane = tid & 31;
    const int g    = lane >> 2;
    const int c    = lane & 3;
    const int row0 = blockIdx.x * 64 + wid * 16;

    // ldmatrix lane addressing: matrix m = lane>>3, matrix row r = lane&7
    const int lm = lane >> 3, lr = lane & 7;

    // --- Preload Q A-fragments (verified mapping from R12) ---
    const uint32_t* q32h = (const uint32_t*)g_qhi + ((size_t)h * SQ + row0) * 32;
    const uint32_t* q32l = (const uint32_t*)g_qlo + ((size_t)h * SQ + row0) * 32;
    uint32_t qh[4][4], ql[4][4];
    #pragma unroll
    for (int ch = 0; ch < 4; ch++) {
        int o0 = g * 32 + 8 * ch + c;
        int o1 = (g + 8) * 32 + 8 * ch + c;
        qh[ch][0] = q32h[o0];     qh[ch][1] = q32h[o1];
        qh[ch][2] = q32h[o0 + 4]; qh[ch][3] = q32h[o1 + 4];
        ql[ch][0] = q32l[o0];     ql[ch][1] = q32l[o1];
        ql[ch][2] = q32l[o0 + 4]; ql[ch][3] = q32l[o1 + 4];
    }

    const uint32_t* k32h = (const uint32_t*)g_khi + (size_t)h * SKV * 32;
    const uint32_t* k32l = (const uint32_t*)g_klo + (size_t)h * SKV * 32;
    const uint32_t* v32h = (const uint32_t*)g_vthi + (size_t)h * DHEAD * (SKV / 2);
    const uint32_t* v32l = (const uint32_t*)g_vtlo + (size_t)h * DHEAD * (SKV / 2);

    float O[8][4];
    #pragma unroll
    for (int j = 0; j < 8; j++)
        #pragma unroll
        for (int k = 0; k < 4; k++) O[j][k] = 0.f;
    float lg = 0.f, lg8 = 0.f;
    const float sc = 0.125f;

    // Per-thread fill coordinates: idx = tid + i*128 -> row = idx>>3, f4 = idx&7
    const int frow = tid >> 3, ff4 = tid & 7;

    for (int t0 = 0; t0 < SKV; t0 += 64) {
        __syncthreads();   // previous tile's fragment reads complete

        // ---- Fill smem tiles (coalesced LDG.128, swizzled STS.128) ----
        #pragma unroll
        for (int i = 0; i < 4; i++) {
            int row = frow + i * 16;
            uint32_t dsw = row * 32 + ((ff4 * 4) ^ ((row & 7) << 2));
            *(float4*)&sKh[dsw] = ((const float4*)(k32h + (size_t)(t0 + row) * 32))[ff4];
            *(float4*)&sKl[dsw] = ((const float4*)(k32l + (size_t)(t0 + row) * 32))[ff4];
            *(float4*)&sVh[dsw] = ((const float4*)(v32h + (size_t)row * (SKV / 2) + (t0 >> 1)))[ff4];
            *(float4*)&sVl[dsw] = ((const float4*)(v32l + (size_t)row * (SKV / 2) + (t0 >> 1)))[ff4];
        }
        __syncthreads();

        // ---- S = Q . K^T : 8 n-blocks of 8 kv ----
        uint32_t pah[4][4], pal[4][4];
        float Sev[4];
        #pragma unroll
        for (int b = 0; b < 8; b++) {
            // B fragments for 4 k16-chunks, hi+lo: 2 ldmatrix.x4 per plane
            uint32_t bh[8], bl[8];
            #pragma unroll
            for (int chp = 0; chp < 2; chp++) {
                int r = 8 * b + lr;
                uint32_t off = r * 32 + (((4 * chp + lm) * 4) ^ ((r & 7) << 2));
                ldsm4(smem_u32(&sKh[off]), &bh[4 * chp]);
                ldsm4(smem_u32(&sKl[off]), &bl[4 * chp]);
            }
            float Sb[4] = {0.f, 0.f, 0.f, 0.f};
            #pragma unroll
            for (int ch = 0; ch < 4; ch++) {
                mma16816(Sb, qh[ch], bh[2 * ch], bh[2 * ch + 1]);
                mma16816(Sb, qh[ch], bl[2 * ch], bl[2 * ch + 1]);
                mma16816(Sb, ql[ch], bh[2 * ch], bh[2 * ch + 1]);
            }
            // p = exp(s/8) (no-max softmax; logits bounded), accumulate sums
            Sb[0] = __expf(Sb[0] * sc); Sb[1] = __expf(Sb[1] * sc);
            Sb[2] = __expf(Sb[2] * sc); Sb[3] = __expf(Sb[3] * sc);
            lg  += Sb[0] + Sb[1];
            lg8 += Sb[2] + Sb[3];
            if ((b & 1) == 0) {
                Sev[0] = Sb[0]; Sev[1] = Sb[1]; Sev[2] = Sb[2]; Sev[3] = Sb[3];
            } else {
                int c2 = b >> 1;   // P A-fragment chunk (verified repack from R12)
                split2(Sev[0], Sev[1], pah[c2][0], pal[c2][0]);
                split2(Sev[2], Sev[3], pah[c2][1], pal[c2][1]);
                split2(Sb[0],  Sb[1],  pah[c2][2], pal[c2][2]);
                split2(Sb[2],  Sb[3],  pah[c2][3], pal[c2][3]);
            }
        }

        // ---- O += P . V : 8 n-blocks of 8 d-cols ----
        #pragma unroll
        for (int j = 0; j < 8; j++) {
            uint32_t vh[8], vl[8];
            #pragma unroll
            for (int chp = 0; chp < 2; chp++) {
                int r = 8 * j + lr;
                uint32_t off = r * 32 + (((4 * chp + lm) * 4) ^ ((r & 7) << 2));
                ldsm4(smem_u32(&sVh[off]), &vh[4 * chp]);
                ldsm4(smem_u32(&sVl[off]), &vl[4 * chp]);
            }
            #pragma unroll
            for (int tc = 0; tc < 4; tc++) {
                mma16816(O[j], pah[tc], vh[2 * tc], vh[2 * tc + 1]);
                mma16816(O[j], pah[tc], vl[2 * tc], vl[2 * tc + 1]);
                mma16816(O[j], pal[tc], vh[2 * tc], vh[2 * tc + 1]);
            }
        }
    }

    // ---- finalize: reduce l across 4 lanes of each row, normalize, store ----
    lg  += __shfl_xor_sync(0xffffffffu, lg, 1);
    lg  += __shfl_xor_sync(0xffffffffu, lg, 2);
    lg8 += __shfl_xor_sync(0xffffffffu, lg8, 1);
    lg8 += __shfl_xor_sync(0xffffffffu, lg8, 2);
    const float ig = 1.f / lg, ig8 = 1.f / lg8;

    float* o0 = g_concat + (size_t)(row0 + g) * DM + h * DHEAD;
    float* o1 = g_concat + (size_t)(row0 + g + 8) * DM + h * DHEAD;
    #pragma unroll
    for (int j = 0; j < 8; j++) {
        *(float2*)(o0 + 8 * j + 2 * c) = make_float2(O[j][0] * ig,  O[j][1] * ig);
        *(float2*)(o1 + 8 * j + 2 * c) = make_float2(O[j][2] * ig8, O[j][3] * ig8);
    }
}

// ---------------------------------------------------------------------------
// Output projection (unchanged; passing).
// ---------------------------------------------------------------------------
__global__ __launch_bounds__(128, 4) void out_proj_kernel(
    const float* __restrict__ Wo,
    const float* __restrict__ bo,
    float* __restrict__ out)
{
    __shared__ float As[32][128];
    __shared__ float Bs[32][64];

    const int s0 = blockIdx.x * 128;
    const int n0 = blockIdx.y * 64;
    const int tid = threadIdx.x;
    const int ty8 = (tid >> 3) << 3;
    const int tx8 = (tid & 7) << 3;

    float acc[8][8];
    #pragma unroll
    for (int i = 0; i < 8; i++)
        #pragma unroll
        for (int j = 0; j < 8; j++) acc[i][j] = 0.f;

    const float* Xrow = g_concat + (size_t)(s0 + tid) * DM;

    for (int kb = 0; kb < DM; kb += 32) {
        #pragma unroll
        for (int i = 0; i < 8; i++) {
            float4 v = *(const float4*)(Xrow + kb + i * 4);
            As[i * 4 + 0][tid] = v.x; As[i * 4 + 1][tid] = v.y;
            As[i * 4 + 2][tid] = v.z; As[i * 4 + 3][tid] = v.w;
        }
        #pragma unroll
        for (int i = 0; i < 4; i++) {
            int t  = tid + i * 128;
            int kk = t >> 4;
            int c4 = (t & 15) << 2;
            *(float4*)&Bs[kk][c4] = *(const float4*)(Wo + (size_t)(kb + kk) * DM + n0 + c4);
        }
        __syncthreads();

        #pragma unroll 8
        for (int kk = 0; kk < 32; kk++) {
            float4 a0 = *(const float4*)&As[kk][ty8];
            float4 a1 = *(const float4*)&As[kk][ty8 + 4];
            float4 c0 = *(const float4*)&Bs[kk][tx8];
            float4 c1 = *(const float4*)&Bs[kk][tx8 + 4];
            float av[8] = {a0.x, a0.y, a0.z, a0.w, a1.x, a1.y, a1.z, a1.w};
            float bv[8] = {c0.x, c0.y, c0.z, c0.w, c1.x, c1.y, c1.z, c1.w};
            #pragma unroll
            for (int i = 0; i < 8; i++)
                #pragma unroll
                for (int j = 0; j < 8; j++)
                    acc[i][j] += av[i] * bv[j];
        }
        __syncthreads();
    }

    float4 bi0 = *(const float4*)(bo + n0 + tx8);
    float4 bi1 = *(const float4*)(bo + n0 + tx8 + 4);
    float bias[8] = {bi0.x, bi0.y, bi0.z, bi0.w, bi1.x, bi1.y, bi1.z, bi1.w};
    #pragma unroll
    for (int i = 0; i < 8; i++) {
        float* orow = out + (size_t)(s0 + ty8 + i) * DM + n0 + tx8;
        *(float4*)orow = make_float4(acc[i][0] + bias[0], acc[i][1] + bias[1],
                                     acc[i][2] + bias[2], acc[i][3] + bias[3]);
        *(float4*)(orow + 4) = make_float4(acc[i][4] + bias[4], acc[i][5] + bias[5],
                                           acc[i][6] + bias[6], acc[i][7] + bias[7]);
    }
}

// ---------------------------------------------------------------------------
// Launch
// ---------------------------------------------------------------------------
extern "C" void kernel_launch(void* const* d_in, const int* in_sizes, int n_in,
                              void* d_out, int out_size)
{
    const float* emb = (const float*)d_in[0];
    const float* K   = (const float*)d_in[1];
    const float* V   = (const float*)d_in[2];
    const float* Wq  = (const float*)d_in[3];
    const float* bq  = (const float*)d_in[4];
    const float* Wk  = (const float*)d_in[5];
    const float* bk  = (const float*)d_in[6];
    const float* Wv  = (const float*)d_in[7];
    const float* bv  = (const float*)d_in[8];
    const float* Wo  = (const float*)d_in[9];
    const float* bo  = (const float*)d_in[10];
    float* out = (float*)d_out;

    proj_qkv_kernel<<<dim3(SQ / 128, NH, 3), 128>>>(
        emb, Wq, bq,
        K,   Wk, bk,
        V,   Wv, bv);

    convert_qk_kernel<<<(NH * SQ * DHEAD / 2) / 256, 256>>>(0);   // q
    convert_qk_kernel<<<(NH * SKV * DHEAD / 2) / 256, 256>>>(1);  // k
    convert_vt_kernel<<<dim3(SKV / 64, NH), 256>>>();

    attn_mma_kernel<<<dim3(SQ / 64, NH), 128>>>();

    out_proj_kernel<<<dim3(SQ / 128, DM / 64), 128>>>(Wo, bo, out);
}

// round 16
// speedup vs baseline: 1.0220x; 1.0220x over previous
#include <cuda_runtime.h>
#include <stdint.h>
#include <math.h>

#define SQ    2048
#define SKV   2048
#define DM    512
#define NH    8
#define DHEAD 64

// ---------------------------------------------------------------------------
// Scratch (device globals: allocation-guard safe)
// ---------------------------------------------------------------------------
__device__ float g_q[NH * SQ * DHEAD];          // [h][s][d] fp32
__device__ float g_k[NH * SKV * DHEAD];         // [h][t][d] fp32
__device__ float g_v[NH * SKV * DHEAD];         // [h][t][d] fp32
__device__ float g_concat[SQ * DM];             // [s][h*64 + c]
// bf16 split planes (hi + residual lo)
__device__ unsigned short g_qhi[NH * SQ * DHEAD],  g_qlo[NH * SQ * DHEAD];
__device__ unsigned short g_khi[NH * SKV * DHEAD], g_klo[NH * SKV * DHEAD];
__device__ unsigned short g_vthi[NH * DHEAD * SKV], g_vtlo[NH * DHEAD * SKV]; // [h][d][t]

// ---------------------------------------------------------------------------
// bf16 split helpers (verified in R12)
// ---------------------------------------------------------------------------
static __device__ __forceinline__ uint32_t bf2pack(float up, float dn) {
    uint32_t r;
    asm("cvt.rn.bf16x2.f32 %0, %1, %2;" : "=r"(r) : "f"(up), "f"(dn));
    return r;
}
static __device__ __forceinline__ float bf_up(uint32_t p) { return __uint_as_float(p & 0xffff0000u); }
static __device__ __forceinline__ float bf_dn(uint32_t p) { return __uint_as_float(p << 16); }
static __device__ __forceinline__ void split2(float x0, float x1, uint32_t& h, uint32_t& l) {
    h = bf2pack(x1, x0);
    l = bf2pack(x1 - bf_up(h), x0 - bf_dn(h));
}
static __device__ __forceinline__ void mma16816(float* d, const uint32_t* a,
                                                uint32_t b0, uint32_t b1) {
    asm("mma.sync.aligned.m16n8k16.row.col.f32.bf16.bf16.f32 "
        "{%0,%1,%2,%3}, {%4,%5,%6,%7}, {%8,%9}, {%0,%1,%2,%3};"
        : "+f"(d[0]), "+f"(d[1]), "+f"(d[2]), "+f"(d[3])
        : "r"(a[0]), "r"(a[1]), "r"(a[2]), "r"(a[3]), "r"(b0), "r"(b1));
}
static __device__ __forceinline__ void ldsm4(uint32_t addr, uint32_t* r) {
    asm volatile("ldmatrix.sync.aligned.m8n8.x4.shared.b16 {%0,%1,%2,%3}, [%4];"
                 : "=r"(r[0]), "=r"(r[1]), "=r"(r[2]), "=r"(r[3]) : "r"(addr));
}
static __device__ __forceinline__ uint32_t smem_u32(const void* p) {
    uint32_t r;
    asm("{ .reg .u64 t; cvta.to.shared.u64 t, %1; cvt.u32.u64 %0, t; }" : "=r"(r) : "l"(p));
    return r;
}

// ---------------------------------------------------------------------------
// Q/K/V projection GEMMs (unchanged; passing).
// ---------------------------------------------------------------------------
__global__ __launch_bounds__(128, 4) void proj_qkv_kernel(
    const float* __restrict__ X0, const float* __restrict__ W0, const float* __restrict__ b0,
    const float* __restrict__ X1, const float* __restrict__ W1, const float* __restrict__ b1,
    const float* __restrict__ X2, const float* __restrict__ W2, const float* __restrict__ b2)
{
    __shared__ float As[32][128];
    __shared__ float Bs[32][64];

    const float* X; const float* W; const float* b; float* out;
    if (blockIdx.z == 0)      { X = X0; W = W0; b = b0; out = g_q; }
    else if (blockIdx.z == 1) { X = X1; W = W1; b = b1; out = g_k; }
    else                      { X = X2; W = W2; b = b2; out = g_v; }

    const int h  = blockIdx.y;
    const int s0 = blockIdx.x * 128;
    const float* Wh = W + (size_t)h * DM * DHEAD;

    const int tid = threadIdx.x;
    const int ty8 = (tid >> 3) << 3;
    const int tx8 = (tid & 7) << 3;

    float acc[8][8];
    #pragma unroll
    for (int i = 0; i < 8; i++)
        #pragma unroll
        for (int j = 0; j < 8; j++) acc[i][j] = 0.f;

    const float* Xrow = X + (size_t)(s0 + tid) * DM;

    for (int kb = 0; kb < DM; kb += 32) {
        #pragma unroll
        for (int i = 0; i < 8; i++) {
            float4 v = *(const float4*)(Xrow + kb + i * 4);
            As[i * 4 + 0][tid] = v.x; As[i * 4 + 1][tid] = v.y;
            As[i * 4 + 2][tid] = v.z; As[i * 4 + 3][tid] = v.w;
        }
        #pragma unroll
        for (int i = 0; i < 4; i++) {
            int t  = tid + i * 128;
            int kk = t >> 4;
            int c4 = (t & 15) << 2;
            *(float4*)&Bs[kk][c4] = *(const float4*)(Wh + (size_t)(kb + kk) * DHEAD + c4);
        }
        __syncthreads();

        #pragma unroll 8
        for (int kk = 0; kk < 32; kk++) {
            float4 a0 = *(const float4*)&As[kk][ty8];
            float4 a1 = *(const float4*)&As[kk][ty8 + 4];
            float4 c0 = *(const float4*)&Bs[kk][tx8];
            float4 c1 = *(const float4*)&Bs[kk][tx8 + 4];
            float av[8] = {a0.x, a0.y, a0.z, a0.w, a1.x, a1.y, a1.z, a1.w};
            float bv[8] = {c0.x, c0.y, c0.z, c0.w, c1.x, c1.y, c1.z, c1.w};
            #pragma unroll
            for (int i = 0; i < 8; i++)
                #pragma unroll
                for (int j = 0; j < 8; j++)
                    acc[i][j] += av[i] * bv[j];
        }
        __syncthreads();
    }

    float4 bi0 = *(const float4*)(b + h * DHEAD + tx8);
    float4 bi1 = *(const float4*)(b + h * DHEAD + tx8 + 4);
    float bias[8] = {bi0.x, bi0.y, bi0.z, bi0.w, bi1.x, bi1.y, bi1.z, bi1.w};
    #pragma unroll
    for (int i = 0; i < 8; i++) {
        float* orow = out + ((size_t)h * SQ + s0 + ty8 + i) * DHEAD + tx8;
        *(float4*)orow = make_float4(acc[i][0] + bias[0], acc[i][1] + bias[1],
                                     acc[i][2] + bias[2], acc[i][3] + bias[3]);
        *(float4*)(orow + 4) = make_float4(acc[i][4] + bias[4], acc[i][5] + bias[5],
                                           acc[i][6] + bias[6], acc[i][7] + bias[7]);
    }
}

// ---------------------------------------------------------------------------
// Convert fp32 q/k -> hi/lo bf16 planes (unchanged; passing).
// ---------------------------------------------------------------------------
__global__ __launch_bounds__(256) void convert_qk_kernel(int which)
{
    const float* src   = which ? g_k : g_q;
    unsigned short* hi = which ? g_khi : g_qhi;
    unsigned short* lo = which ? g_klo : g_qlo;
    int i = blockIdx.x * 256 + threadIdx.x;
    float2 x = ((const float2*)src)[i];
    uint32_t hh, ll;
    split2(x.x, x.y, hh, ll);
    ((uint32_t*)hi)[i] = hh;
    ((uint32_t*)lo)[i] = ll;
}

// ---------------------------------------------------------------------------
// Convert + transpose V (unchanged; passing).
// ---------------------------------------------------------------------------
__global__ __launch_bounds__(256) void convert_vt_kernel()
{
    __shared__ float sm[64][65];
    const int h = blockIdx.y, t0 = blockIdx.x * 64;
    const int tid = threadIdx.x;
    const float* Vh = g_v + ((size_t)h * SKV + t0) * DHEAD;

    #pragma unroll
    for (int i = 0; i < 4; i++) {
        int fi = tid + i * 256;
        int t = fi >> 4, d4 = (fi & 15) << 2;
        float4 v = *(const float4*)(Vh + t * DHEAD + d4);
        sm[t][d4 + 0] = v.x; sm[t][d4 + 1] = v.y;
        sm[t][d4 + 2] = v.z; sm[t][d4 + 3] = v.w;
    }
    __syncthreads();

    uint32_t* oh = (uint32_t*)g_vthi;
    uint32_t* ol = (uint32_t*)g_vtlo;
    #pragma unroll
    for (int i = 0; i < 8; i++) {
        int oi = tid + i * 256;
        int d = oi >> 5, tp = oi & 31;
        float x0 = sm[2 * tp][d], x1 = sm[2 * tp + 1][d];
        uint32_t hh, ll;
        split2(x0, x1, hh, ll);
        size_t idx = ((size_t)h * 64 + d) * (SKV / 2) + (t0 >> 1) + tp;
        oh[idx] = hh;
        ol[idx] = ll;
    }
}

// ---------------------------------------------------------------------------
// bf16x3 tensor-core flash attention, smem-staged K/V + ldmatrix fragments.
// grid = (SQ/64, NH); block = 128 (4 warps x 16 q-rows); kv tile = 64.
// Swizzle: u32 offset = row*32 + ((f4*4) ^ ((row&7)<<2))  [16B-granular XOR]
// ---------------------------------------------------------------------------
__global__ __launch_bounds__(128) void attn_mma_kernel()
{
    __shared__ uint32_t sKh[64 * 32], sKl[64 * 32], sVh[64 * 32], sVl[64 * 32]; // 32 KB

    const int h    = blockIdx.y;
    const int tid  = threadIdx.x;
    const int wid  = tid >> 5, lane = tid & 31;
    const int g    = lane >> 2;
    const int c    = lane & 3;
    const int row0 = blockIdx.x * 64 + wid * 16;

    // ldmatrix lane addressing: matrix m = lane>>3, matrix row r = lane&7
    const int lm = lane >> 3, lr = lane & 7;

    // --- Preload Q A-fragments (verified mapping from R12) ---
    const uint32_t* q32h = (const uint32_t*)g_qhi + ((size_t)h * SQ + row0) * 32;
    const uint32_t* q32l = (const uint32_t*)g_qlo + ((size_t)h * SQ + row0) * 32;
    uint32_t qh[4][4], ql[4][4];
    #pragma unroll
    for (int ch = 0; ch < 4; ch++) {
        int o0 = g * 32 + 8 * ch + c;
        int o1 = (g + 8) * 32 + 8 * ch + c;
        qh[ch][0] = q32h[o0];     qh[ch][1] = q32h[o1];
        qh[ch][2] = q32h[o0 + 4]; qh[ch][3] = q32h[o1 + 4];
        ql[ch][0] = q32l[o0];     ql[ch][1] = q32l[o1];
        ql[ch][2] = q32l[o0 + 4]; ql[ch][3] = q32l[o1 + 4];
    }

    const uint32_t* k32h = (const uint32_t*)g_khi + (size_t)h * SKV * 32;
    const uint32_t* k32l = (const uint32_t*)g_klo + (size_t)h * SKV * 32;
    const uint32_t* v32h = (const uint32_t*)g_vthi + (size_t)h * DHEAD * (SKV / 2);
    const uint32_t* v32l = (const uint32_t*)g_vtlo + (size_t)h * DHEAD * (SKV / 2);

    float O[8][4];
    #pragma unroll
    for (int j = 0; j < 8; j++)
        #pragma unroll
        for (int k = 0; k < 4; k++) O[j][k] = 0.f;
    float lg = 0.f, lg8 = 0.f;
    const float sc = 0.125f;

    // Per-thread fill coordinates: idx = tid + i*128 -> row = idx>>3, f4 = idx&7
    const int frow = tid >> 3, ff4 = tid & 7;

    for (int t0 = 0; t0 < SKV; t0 += 64) {
        __syncthreads();   // previous tile's fragment reads complete

        // ---- Fill smem tiles (coalesced LDG.128, swizzled STS.128) ----
        #pragma unroll
        for (int i = 0; i < 4; i++) {
            int row = frow + i * 16;
            uint32_t dsw = row * 32 + ((ff4 * 4) ^ ((row & 7) << 2));
            *(float4*)&sKh[dsw] = ((const float4*)(k32h + (size_t)(t0 + row) * 32))[ff4];
            *(float4*)&sKl[dsw] = ((const float4*)(k32l + (size_t)(t0 + row) * 32))[ff4];
            *(float4*)&sVh[dsw] = ((const float4*)(v32h + (size_t)row * (SKV / 2) + (t0 >> 1)))[ff4];
            *(float4*)&sVl[dsw] = ((const float4*)(v32l + (size_t)row * (SKV / 2) + (t0 >> 1)))[ff4];
        }
        __syncthreads();

        // ---- S = Q . K^T : 8 n-blocks of 8 kv ----
        uint32_t pah[4][4], pal[4][4];
        float Sev[4];
        #pragma unroll
        for (int b = 0; b < 8; b++) {
            // B fragments for 4 k16-chunks, hi+lo: 2 ldmatrix.x4 per plane
            uint32_t bh[8], bl[8];
            #pragma unroll
            for (int chp = 0; chp < 2; chp++) {
                int r = 8 * b + lr;
                uint32_t off = r * 32 + (((4 * chp + lm) * 4) ^ ((r & 7) << 2));
                ldsm4(smem_u32(&sKh[off]), &bh[4 * chp]);
                ldsm4(smem_u32(&sKl[off]), &bl[4 * chp]);
            }
            float Sb[4] = {0.f, 0.f, 0.f, 0.f};
            #pragma unroll
            for (int ch = 0; ch < 4; ch++) {
                mma16816(Sb, qh[ch], bh[2 * ch], bh[2 * ch + 1]);
                mma16816(Sb, qh[ch], bl[2 * ch], bl[2 * ch + 1]);
                mma16816(Sb, ql[ch], bh[2 * ch], bh[2 * ch + 1]);
            }
            // p = exp(s/8) (no-max softmax; logits bounded), accumulate sums
            Sb[0] = __expf(Sb[0] * sc); Sb[1] = __expf(Sb[1] * sc);
            Sb[2] = __expf(Sb[2] * sc); Sb[3] = __expf(Sb[3] * sc);
            lg  += Sb[0] + Sb[1];
            lg8 += Sb[2] + Sb[3];
            if ((b & 1) == 0) {
                Sev[0] = Sb[0]; Sev[1] = Sb[1]; Sev[2] = Sb[2]; Sev[3] = Sb[3];
            } else {
                int c2 = b >> 1;   // P A-fragment chunk (verified repack from R12)
                split2(Sev[0], Sev[1], pah[c2][0], pal[c2][0]);
                split2(Sev[2], Sev[3], pah[c2][1], pal[c2][1]);
                split2(Sb[0],  Sb[1],  pah[c2][2], pal[c2][2]);
                split2(Sb[2],  Sb[3],  pah[c2][3], pal[c2][3]);
            }
        }

        // ---- O += P . V : 8 n-blocks of 8 d-cols ----
        #pragma unroll
        for (int j = 0; j < 8; j++) {
            uint32_t vh[8], vl[8];
            #pragma unroll
            for (int chp = 0; chp < 2; chp++) {
                int r = 8 * j + lr;
                uint32_t off = r * 32 + (((4 * chp + lm) * 4) ^ ((r & 7) << 2));
                ldsm4(smem_u32(&sVh[off]), &vh[4 * chp]);
                ldsm4(smem_u32(&sVl[off]), &vl[4 * chp]);
            }
            #pragma unroll
            for (int tc = 0; tc < 4; tc++) {
                mma16816(O[j], pah[tc], vh[2 * tc], vh[2 * tc + 1]);
                mma16816(O[j], pah[tc], vl[2 * tc], vl[2 * tc + 1]);
                mma16816(O[j], pal[tc], vh[2 * tc], vh[2 * tc + 1]);
            }
        }
    }

    // ---- finalize: reduce l across 4 lanes of each row, normalize, store ----
    lg  += __shfl_xor_sync(0xffffffffu, lg, 1);
    lg  += __shfl_xor_sync(0xffffffffu, lg, 2);
    lg8 += __shfl_xor_sync(0xffffffffu, lg8, 1);
    lg8 += __shfl_xor_sync(0xffffffffu, lg8, 2);
    const float ig = 1.f / lg, ig8 = 1.f / lg8;

    float* o0 = g_concat + (size_t)(row0 + g) * DM + h * DHEAD;
    float* o1 = g_concat + (size_t)(row0 + g + 8) * DM + h * DHEAD;
    #pragma unroll
    for (int j = 0; j < 8; j++) {
        *(float2*)(o0 + 8 * j + 2 * c) = make_float2(O[j][0] * ig,  O[j][1] * ig);
        *(float2*)(o1 + 8 * j + 2 * c) = make_float2(O[j][2] * ig8, O[j][3] * ig8);
    }
}

// ---------------------------------------------------------------------------
// Output projection (unchanged; passing).
// ---------------------------------------------------------------------------
__global__ __launch_bounds__(128, 4) void out_proj_kernel(
    const float* __restrict__ Wo,
    const float* __restrict__ bo,
    float* __restrict__ out)
{
    __shared__ float As[32][128];
    __shared__ float Bs[32][64];

    const int s0 = blockIdx.x * 128;
    const int n0 = blockIdx.y * 64;
    const int tid = threadIdx.x;
    const int ty8 = (tid >> 3) << 3;
    const int tx8 = (tid & 7) << 3;

    float acc[8][8];
    #pragma unroll
    for (int i = 0; i < 8; i++)
        #pragma unroll
        for (int j = 0; j < 8; j++) acc[i][j] = 0.f;

    const float* Xrow = g_concat + (size_t)(s0 + tid) * DM;

    for (int kb = 0; kb < DM; kb += 32) {
        #pragma unroll
        for (int i = 0; i < 8; i++) {
            float4 v = *(const float4*)(Xrow + kb + i * 4);
            As[i * 4 + 0][tid] = v.x; As[i * 4 + 1][tid] = v.y;
            As[i * 4 + 2][tid] = v.z; As[i * 4 + 3][tid] = v.w;
        }
        #pragma unroll
        for (int i = 0; i < 4; i++) {
            int t  = tid + i * 128;
            int kk = t >> 4;
            int c4 = (t & 15) << 2;
            *(float4*)&Bs[kk][c4] = *(const float4*)(Wo + (size_t)(kb + kk) * DM + n0 + c4);
        }
        __syncthreads();

        #pragma unroll 8
        for (int kk = 0; kk < 32; kk++) {
            float4 a0 = *(const float4*)&As[kk][ty8];
            float4 a1 = *(const float4*)&As[kk][ty8 + 4];
            float4 c0 = *(const float4*)&Bs[kk][tx8];
            float4 c1 = *(const float4*)&Bs[kk][tx8 + 4];
            float av[8] = {a0.x, a0.y, a0.z, a0.w, a1.x, a1.y, a1.z, a1.w};
            float bv[8] = {c0.x, c0.y, c0.z, c0.w, c1.x, c1.y, c1.z, c1.w};
            #pragma unroll
            for (int i = 0; i < 8; i++)
                #pragma unroll
                for (int j = 0; j < 8; j++)
                    acc[i][j] += av[i] * bv[j];
        }
        __syncthreads();
    }

    float4 bi0 = *(const float4*)(bo + n0 + tx8);
    float4 bi1 = *(const float4*)(bo + n0 + tx8 + 4);
    float bias[8] = {bi0.x, bi0.y, bi0.z, bi0.w, bi1.x, bi1.y, bi1.z, bi1.w};
    #pragma unroll
    for (int i = 0; i < 8; i++) {
        float* orow = out + (size_t)(s0 + ty8 + i) * DM + n0 + tx8;
        *(float4*)orow = make_float4(acc[i][0] + bias[0], acc[i][1] + bias[1],
                                     acc[i][2] + bias[2], acc[i][3] + bias[3]);
        *(float4*)(orow + 4) = make_float4(acc[i][4] + bias[4], acc[i][5] + bias[5],
                                           acc[i][6] + bias[6], acc[i][7] + bias[7]);
    }
}

// ---------------------------------------------------------------------------
// Launch
// ---------------------------------------------------------------------------
extern "C" void kernel_launch(void* const* d_in, const int* in_sizes, int n_in,
                              void* d_out, int out_size)
{
    const float* emb = (const float*)d_in[0];
    const float* K   = (const float*)d_in[1];
    const float* V   = (const float*)d_in[2];
    const float* Wq  = (const float*)d_in[3];
    const float* bq  = (const float*)d_in[4];
    const float* Wk  = (const float*)d_in[5];
    const float* bk  = (const float*)d_in[6];
    const float* Wv  = (const float*)d_in[7];
    const float* bv  = (const float*)d_in[8];
    const float* Wo  = (const float*)d_in[9];
    const float* bo  = (const float*)d_in[10];
    float* out = (float*)d_out;

    proj_qkv_kernel<<<dim3(SQ / 128, NH, 3), 128>>>(
        emb, Wq, bq,
        K,   Wk, bk,
        V,   Wv, bv);

    convert_qk_kernel<<<(NH * SQ * DHEAD / 2) / 256, 256>>>(0);   // q
    convert_qk_kernel<<<(NH * SKV * DHEAD / 2) / 256, 256>>>(1);  // k
    convert_vt_kernel<<<dim3(SKV / 64, NH), 256>>>();

    attn_mma_kernel<<<dim3(SQ / 64, NH), 128>>>();

    out_proj_kernel<<<dim3(SQ / 128, DM / 64), 128>>>(Wo, bo, out);
}

// round 17
// speedup vs baseline: 1.0227x; 1.0007x over previous
#include <cuda_runtime.h>
#include <stdint.h>
#include <math.h>

#define SQ    2048
#define SKV   2048
#define DM    512
#define NH    8
#define DHEAD 64

// ---------------------------------------------------------------------------
// Scratch (device globals: allocation-guard safe)
// ---------------------------------------------------------------------------
__device__ float g_q[NH * SQ * DHEAD];          // [h][s][d] fp32
__device__ float g_k[NH * SKV * DHEAD];         // [h][t][d] fp32
__device__ float g_v[NH * SKV * DHEAD];         // [h][t][d] fp32
__device__ float g_concat[SQ * DM];             // [s][h*64 + c]
// bf16 split planes (hi + residual lo)
__device__ unsigned short g_qhi[NH * SQ * DHEAD],  g_qlo[NH * SQ * DHEAD];
__device__ unsigned short g_khi[NH * SKV * DHEAD], g_klo[NH * SKV * DHEAD];
__device__ unsigned short g_vthi[NH * DHEAD * SKV], g_vtlo[NH * DHEAD * SKV]; // [h][d][t]

// ---------------------------------------------------------------------------
// bf16 split helpers (verified in R12)
// ---------------------------------------------------------------------------
static __device__ __forceinline__ uint32_t bf2pack(float up, float dn) {
    uint32_t r;
    asm("cvt.rn.bf16x2.f32 %0, %1, %2;" : "=r"(r) : "f"(up), "f"(dn));
    return r;
}
static __device__ __forceinline__ float bf_up(uint32_t p) { return __uint_as_float(p & 0xffff0000u); }
static __device__ __forceinline__ float bf_dn(uint32_t p) { return __uint_as_float(p << 16); }
static __device__ __forceinline__ void split2(float x0, float x1, uint32_t& h, uint32_t& l) {
    h = bf2pack(x1, x0);
    l = bf2pack(x1 - bf_up(h), x0 - bf_dn(h));
}
static __device__ __forceinline__ void mma16816(float* d, const uint32_t* a,
                                                uint32_t b0, uint32_t b1) {
    asm("mma.sync.aligned.m16n8k16.row.col.f32.bf16.bf16.f32 "
        "{%0,%1,%2,%3}, {%4,%5,%6,%7}, {%8,%9}, {%0,%1,%2,%3};"
        : "+f"(d[0]), "+f"(d[1]), "+f"(d[2]), "+f"(d[3])
        : "r"(a[0]), "r"(a[1]), "r"(a[2]), "r"(a[3]), "r"(b0), "r"(b1));
}
static __device__ __forceinline__ void ldsm4(uint32_t addr, uint32_t* r) {
    asm volatile("ldmatrix.sync.aligned.m8n8.x4.shared.b16 {%0,%1,%2,%3}, [%4];"
                 : "=r"(r[0]), "=r"(r[1]), "=r"(r[2]), "=r"(r[3]) : "r"(addr));
}
static __device__ __forceinline__ uint32_t smem_u32(const void* p) {
    uint32_t r;
    asm("{ .reg .u64 t; cvta.to.shared.u64 t, %1; cvt.u32.u64 %0, t; }" : "=r"(r) : "l"(p));
    return r;
}

// ---------------------------------------------------------------------------
// Q/K/V projection GEMMs (unchanged; passing).
// ---------------------------------------------------------------------------
__global__ __launch_bounds__(128, 4) void proj_qkv_kernel(
    const float* __restrict__ X0, const float* __restrict__ W0, const float* __restrict__ b0,
    const float* __restrict__ X1, const float* __restrict__ W1, const float* __restrict__ b1,
    const float* __restrict__ X2, const float* __restrict__ W2, const float* __restrict__ b2)
{
    __shared__ float As[32][128];
    __shared__ float Bs[32][64];

    const float* X; const float* W; const float* b; float* out;
    if (blockIdx.z == 0)      { X = X0; W = W0; b = b0; out = g_q; }
    else if (blockIdx.z == 1) { X = X1; W = W1; b = b1; out = g_k; }
    else                      { X = X2; W = W2; b = b2; out = g_v; }

    const int h  = blockIdx.y;
    const int s0 = blockIdx.x * 128;
    const float* Wh = W + (size_t)h * DM * DHEAD;

    const int tid = threadIdx.x;
    const int ty8 = (tid >> 3) << 3;
    const int tx8 = (tid & 7) << 3;

    float acc[8][8];
    #pragma unroll
    for (int i = 0; i < 8; i++)
        #pragma unroll
        for (int j = 0; j < 8; j++) acc[i][j] = 0.f;

    const float* Xrow = X + (size_t)(s0 + tid) * DM;

    for (int kb = 0; kb < DM; kb += 32) {
        #pragma unroll
        for (int i = 0; i < 8; i++) {
            float4 v = *(const float4*)(Xrow + kb + i * 4);
            As[i * 4 + 0][tid] = v.x; As[i * 4 + 1][tid] = v.y;
            As[i * 4 + 2][tid] = v.z; As[i * 4 + 3][tid] = v.w;
        }
        #pragma unroll
        for (int i = 0; i < 4; i++) {
            int t  = tid + i * 128;
            int kk = t >> 4;
            int c4 = (t & 15) << 2;
            *(float4*)&Bs[kk][c4] = *(const float4*)(Wh + (size_t)(kb + kk) * DHEAD + c4);
        }
        __syncthreads();

        #pragma unroll 8
        for (int kk = 0; kk < 32; kk++) {
            float4 a0 = *(const float4*)&As[kk][ty8];
            float4 a1 = *(const float4*)&As[kk][ty8 + 4];
            float4 c0 = *(const float4*)&Bs[kk][tx8];
            float4 c1 = *(const float4*)&Bs[kk][tx8 + 4];
            float av[8] = {a0.x, a0.y, a0.z, a0.w, a1.x, a1.y, a1.z, a1.w};
            float bv[8] = {c0.x, c0.y, c0.z, c0.w, c1.x, c1.y, c1.z, c1.w};
            #pragma unroll
            for (int i = 0; i < 8; i++)
                #pragma unroll
                for (int j = 0; j < 8; j++)
                    acc[i][j] += av[i] * bv[j];
        }
        __syncthreads();
    }

    float4 bi0 = *(const float4*)(b + h * DHEAD + tx8);
    float4 bi1 = *(const float4*)(b + h * DHEAD + tx8 + 4);
    float bias[8] = {bi0.x, bi0.y, bi0.z, bi0.w, bi1.x, bi1.y, bi1.z, bi1.w};
    #pragma unroll
    for (int i = 0; i < 8; i++) {
        float* orow = out + ((size_t)h * SQ + s0 + ty8 + i) * DHEAD + tx8;
        *(float4*)orow = make_float4(acc[i][0] + bias[0], acc[i][1] + bias[1],
                                     acc[i][2] + bias[2], acc[i][3] + bias[3]);
        *(float4*)(orow + 4) = make_float4(acc[i][4] + bias[4], acc[i][5] + bias[5],
                                           acc[i][6] + bias[6], acc[i][7] + bias[7]);
    }
}

// ---------------------------------------------------------------------------
// Convert fp32 q/k -> hi/lo bf16 planes (unchanged; passing).
// ---------------------------------------------------------------------------
__global__ __launch_bounds__(256) void convert_qk_kernel(int which)
{
    const float* src   = which ? g_k : g_q;
    unsigned short* hi = which ? g_khi : g_qhi;
    unsigned short* lo = which ? g_klo : g_qlo;
    int i = blockIdx.x * 256 + threadIdx.x;
    float2 x = ((const float2*)src)[i];
    uint32_t hh, ll;
    split2(x.x, x.y, hh, ll);
    ((uint32_t*)hi)[i] = hh;
    ((uint32_t*)lo)[i] = ll;
}

// ---------------------------------------------------------------------------
// Convert + transpose V (unchanged; passing).
// ---------------------------------------------------------------------------
__global__ __launch_bounds__(256) void convert_vt_kernel()
{
    __shared__ float sm[64][65];
    const int h = blockIdx.y, t0 = blockIdx.x * 64;
    const int tid = threadIdx.x;
    const float* Vh = g_v + ((size_t)h * SKV + t0) * DHEAD;

    #pragma unroll
    for (int i = 0; i < 4; i++) {
        int fi = tid + i * 256;
        int t = fi >> 4, d4 = (fi & 15) << 2;
        float4 v = *(const float4*)(Vh + t * DHEAD + d4);
        sm[t][d4 + 0] = v.x; sm[t][d4 + 1] = v.y;
        sm[t][d4 + 2] = v.z; sm[t][d4 + 3] = v.w;
    }
    __syncthreads();

    uint32_t* oh = (uint32_t*)g_vthi;
    uint32_t* ol = (uint32_t*)g_vtlo;
    #pragma unroll
    for (int i = 0; i < 8; i++) {
        int oi = tid + i * 256;
        int d = oi >> 5, tp = oi & 31;
        float x0 = sm[2 * tp][d], x1 = sm[2 * tp + 1][d];
        uint32_t hh, ll;
        split2(x0, x1, hh, ll);
        size_t idx = ((size_t)h * 64 + d) * (SKV / 2) + (t0 >> 1) + tp;
        oh[idx] = hh;
        ol[idx] = ll;
    }
}

// ---------------------------------------------------------------------------
// bf16x3 tensor-core flash attention, smem-staged K/V + ldmatrix fragments.
// grid = (SQ/64, NH); block = 128 (4 warps x 16 q-rows); kv tile = 64.
// Swizzle: u32 offset = row*32 + ((f4*4) ^ ((row&7)<<2))  [16B-granular XOR]
// ---------------------------------------------------------------------------
__global__ __launch_bounds__(128) void attn_mma_kernel()
{
    __shared__ uint32_t sKh[64 * 32], sKl[64 * 32], sVh[64 * 32], sVl[64 * 32]; // 32 KB

    const int h    = blockIdx.y;
    const int tid  = threadIdx.x;
    const int wid  = tid >> 5, lane = tid & 31;
    const int g    = lane >> 2;
    const int c    = lane & 3;
    const int row0 = blockIdx.x * 64 + wid * 16;

    // ldmatrix lane addressing: matrix m = lane>>3, matrix row r = lane&7
    const int lm = lane >> 3, lr = lane & 7;

    // --- Preload Q A-fragments (verified mapping from R12) ---
    const uint32_t* q32h = (const uint32_t*)g_qhi + ((size_t)h * SQ + row0) * 32;
    const uint32_t* q32l = (const uint32_t*)g_qlo + ((size_t)h * SQ + row0) * 32;
    uint32_t qh[4][4], ql[4][4];
    #pragma unroll
    for (int ch = 0; ch < 4; ch++) {
        int o0 = g * 32 + 8 * ch + c;
        int o1 = (g + 8) * 32 + 8 * ch + c;
        qh[ch][0] = q32h[o0];     qh[ch][1] = q32h[o1];
        qh[ch][2] = q32h[o0 + 4]; qh[ch][3] = q32h[o1 + 4];
        ql[ch][0] = q32l[o0];     ql[ch][1] = q32l[o1];
        ql[ch][2] = q32l[o0 + 4]; ql[ch][3] = q32l[o1 + 4];
    }

    const uint32_t* k32h = (const uint32_t*)g_khi + (size_t)h * SKV * 32;
    const uint32_t* k32l = (const uint32_t*)g_klo + (size_t)h * SKV * 32;
    const uint32_t* v32h = (const uint32_t*)g_vthi + (size_t)h * DHEAD * (SKV / 2);
    const uint32_t* v32l = (const uint32_t*)g_vtlo + (size_t)h * DHEAD * (SKV / 2);

    float O[8][4];
    #pragma unroll
    for (int j = 0; j < 8; j++)
        #pragma unroll
        for (int k = 0; k < 4; k++) O[j][k] = 0.f;
    float lg = 0.f, lg8 = 0.f;
    const float sc = 0.125f;

    // Per-thread fill coordinates: idx = tid + i*128 -> row = idx>>3, f4 = idx&7
    const int frow = tid >> 3, ff4 = tid & 7;

    for (int t0 = 0; t0 < SKV; t0 += 64) {
        __syncthreads();   // previous tile's fragment reads complete

        // ---- Fill smem tiles (coalesced LDG.128, swizzled STS.128) ----
        #pragma unroll
        for (int i = 0; i < 4; i++) {
            int row = frow + i * 16;
            uint32_t dsw = row * 32 + ((ff4 * 4) ^ ((row & 7) << 2));
            *(float4*)&sKh[dsw] = ((const float4*)(k32h + (size_t)(t0 + row) * 32))[ff4];
            *(float4*)&sKl[dsw] = ((const float4*)(k32l + (size_t)(t0 + row) * 32))[ff4];
            *(float4*)&sVh[dsw] = ((const float4*)(v32h + (size_t)row * (SKV / 2) + (t0 >> 1)))[ff4];
            *(float4*)&sVl[dsw] = ((const float4*)(v32l + (size_t)row * (SKV / 2) + (t0 >> 1)))[ff4];
        }
        __syncthreads();

        // ---- S = Q . K^T : 8 n-blocks of 8 kv ----
        uint32_t pah[4][4], pal[4][4];
        float Sev[4];
        #pragma unroll
        for (int b = 0; b < 8; b++) {
            // B fragments for 4 k16-chunks, hi+lo: 2 ldmatrix.x4 per plane
            uint32_t bh[8], bl[8];
            #pragma unroll
            for (int chp = 0; chp < 2; chp++) {
                int r = 8 * b + lr;
                uint32_t off = r * 32 + (((4 * chp + lm) * 4) ^ ((r & 7) << 2));
                ldsm4(smem_u32(&sKh[off]), &bh[4 * chp]);
                ldsm4(smem_u32(&sKl[off]), &bl[4 * chp]);
            }
            float Sb[4] = {0.f, 0.f, 0.f, 0.f};
            #pragma unroll
            for (int ch = 0; ch < 4; ch++) {
                mma16816(Sb, qh[ch], bh[2 * ch], bh[2 * ch + 1]);
                mma16816(Sb, qh[ch], bl[2 * ch], bl[2 * ch + 1]);
                mma16816(Sb, ql[ch], bh[2 * ch], bh[2 * ch + 1]);
            }
            // p = exp(s/8) (no-max softmax; logits bounded), accumulate sums
            Sb[0] = __expf(Sb[0] * sc); Sb[1] = __expf(Sb[1] * sc);
            Sb[2] = __expf(Sb[2] * sc); Sb[3] = __expf(Sb[3] * sc);
            lg  += Sb[0] + Sb[1];
            lg8 += Sb[2] + Sb[3];
            if ((b & 1) == 0) {
                Sev[0] = Sb[0]; Sev[1] = Sb[1]; Sev[2] = Sb[2]; Sev[3] = Sb[3];
            } else {
                int c2 = b >> 1;   // P A-fragment chunk (verified repack from R12)
                split2(Sev[0], Sev[1], pah[c2][0], pal[c2][0]);
                split2(Sev[2], Sev[3], pah[c2][1], pal[c2][1]);
                split2(Sb[0],  Sb[1],  pah[c2][2], pal[c2][2]);
                split2(Sb[2],  Sb[3],  pah[c2][3], pal[c2][3]);
            }
        }

        // ---- O += P . V : 8 n-blocks of 8 d-cols ----
        #pragma unroll
        for (int j = 0; j < 8; j++) {
            uint32_t vh[8], vl[8];
            #pragma unroll
            for (int chp = 0; chp < 2; chp++) {
                int r = 8 * j + lr;
                uint32_t off = r * 32 + (((4 * chp + lm) * 4) ^ ((r & 7) << 2));
                ldsm4(smem_u32(&sVh[off]), &vh[4 * chp]);
                ldsm4(smem_u32(&sVl[off]), &vl[4 * chp]);
            }
            #pragma unroll
            for (int tc = 0; tc < 4; tc++) {
                mma16816(O[j], pah[tc], vh[2 * tc], vh[2 * tc + 1]);
                mma16816(O[j], pah[tc], vl[2 * tc], vl[2 * tc + 1]);
                mma16816(O[j], pal[tc], vh[2 * tc], vh[2 * tc + 1]);
            }
        }
    }

    // ---- finalize: reduce l across 4 lanes of each row, normalize, store ----
    lg  += __shfl_xor_sync(0xffffffffu, lg, 1);
    lg  += __shfl_xor_sync(0xffffffffu, lg, 2);
    lg8 += __shfl_xor_sync(0xffffffffu, lg8, 1);
    lg8 += __shfl_xor_sync(0xffffffffu, lg8, 2);
    const float ig = 1.f / lg, ig8 = 1.f / lg8;

    float* o0 = g_concat + (size_t)(row0 + g) * DM + h * DHEAD;
    float* o1 = g_concat + (size_t)(row0 + g + 8) * DM + h * DHEAD;
    #pragma unroll
    for (int j = 0; j < 8; j++) {
        *(float2*)(o0 + 8 * j + 2 * c) = make_float2(O[j][0] * ig,  O[j][1] * ig);
        *(float2*)(o1 + 8 * j + 2 * c) = make_float2(O[j][2] * ig8, O[j][3] * ig8);
    }
}

// ---------------------------------------------------------------------------
// Output projection (unchanged; passing).
// ---------------------------------------------------------------------------
__global__ __launch_bounds__(128, 4) void out_proj_kernel(
    const float* __restrict__ Wo,
    const float* __restrict__ bo,
    float* __restrict__ out)
{
    __shared__ float As[32][128];
    __shared__ float Bs[32][64];

    const int s0 = blockIdx.x * 128;
    const int n0 = blockIdx.y * 64;
    const int tid = threadIdx.x;
    const int ty8 = (tid >> 3) << 3;
    const int tx8 = (tid & 7) << 3;

    float acc[8][8];
    #pragma unroll
    for (int i = 0; i < 8; i++)
        #pragma unroll
        for (int j = 0; j < 8; j++) acc[i][j] = 0.f;

    const float* Xrow = g_concat + (size_t)(s0 + tid) * DM;

    for (int kb = 0; kb < DM; kb += 32) {
        #pragma unroll
        for (int i = 0; i < 8; i++) {
            float4 v = *(const float4*)(Xrow + kb + i * 4);
            As[i * 4 + 0][tid] = v.x; As[i * 4 + 1][tid] = v.y;
            As[i * 4 + 2][tid] = v.z; As[i * 4 + 3][tid] = v.w;
        }
        #pragma unroll
        for (int i = 0; i < 4; i++) {
            int t  = tid + i * 128;
            int kk = t >> 4;
            int c4 = (t & 15) << 2;
            *(float4*)&Bs[kk][c4] = *(const float4*)(Wo + (size_t)(kb + kk) * DM + n0 + c4);
        }
        __syncthreads();

        #pragma unroll 8
        for (int kk = 0; kk < 32; kk++) {
            float4 a0 = *(const float4*)&As[kk][ty8];
            float4 a1 = *(const float4*)&As[kk][ty8 + 4];
            float4 c0 = *(const float4*)&Bs[kk][tx8];
            float4 c1 = *(const float4*)&Bs[kk][tx8 + 4];
            float av[8] = {a0.x, a0.y, a0.z, a0.w, a1.x, a1.y, a1.z, a1.w};
            float bv[8] = {c0.x, c0.y, c0.z, c0.w, c1.x, c1.y, c1.z, c1.w};
            #pragma unroll
            for (int i = 0; i < 8; i++)
                #pragma unroll
                for (int j = 0; j < 8; j++)
                    acc[i][j] += av[i] * bv[j];
        }
        __syncthreads();
    }

    float4 bi0 = *(const float4*)(bo + n0 + tx8);
    float4 bi1 = *(const float4*)(bo + n0 + tx8 + 4);
    float bias[8] = {bi0.x, bi0.y, bi0.z, bi0.w, bi1.x, bi1.y, bi1.z, bi1.w};
    #pragma unroll
    for (int i = 0; i < 8; i++) {
        float* orow = out + (size_t)(s0 + ty8 + i) * DM + n0 + tx8;
        *(float4*)orow = make_float4(acc[i][0] + bias[0], acc[i][1] + bias[1],
                                     acc[i][2] + bias[2], acc[i][3] + bias[3]);
        *(float4*)(orow + 4) = make_float4(acc[i][4] + bias[4], acc[i][5] + bias[5],
                                           acc[i][6] + bias[6], acc[i][7] + bias[7]);
    }
}

// ---------------------------------------------------------------------------
// Launch
// ---------------------------------------------------------------------------
extern "C" void kernel_launch(void* const* d_in, const int* in_sizes, int n_in,
                              void* d_out, int out_size)
{
    const float* emb = (const float*)d_in[0];
    const float* K   = (const float*)d_in[1];
    const float* V   = (const float*)d_in[2];
    const float* Wq  = (const float*)d_in[3];
    const float* bq  = (const float*)d_in[4];
    const float* Wk  = (const float*)d_in[5];
    const float* bk  = (const float*)d_in[6];
    const float* Wv  = (const float*)d_in[7];
    const float* bv  = (const float*)d_in[8];
    const float* Wo  = (const float*)d_in[9];
    const float* bo  = (const float*)d_in[10];
    float* out = (float*)d_out;

    proj_qkv_kernel<<<dim3(SQ / 128, NH, 3), 128>>>(
        emb, Wq, bq,
        K,   Wk, bk,
        V,   Wv, bv);

    convert_qk_kernel<<<(NH * SQ * DHEAD / 2) / 256, 256>>>(0);   // q
    convert_qk_kernel<<<(NH * SKV * DHEAD / 2) / 256, 256>>>(1);  // k
    convert_vt_kernel<<<dim3(SKV / 64, NH), 256>>>();

    attn_mma_kernel<<<dim3(SQ / 64, NH), 128>>>();

    out_proj_kernel<<<dim3(SQ / 128, DM / 64), 128>>>(Wo, bo, out);
}